// round 15
// baseline (speedup 1.0000x reference)
#include <cuda_runtime.h>
#include <cuda_fp16.h>
#include <cstdint>

#define NTOK 8192
#define TOPK 2
#define NEXP 8
#define KDIM 512
#define NDIM 1024
#define MROWS (NTOK * TOPK)

#define TILE_M 128
#define TILE_N 128
#define CH_K   64                          // fp16 K elems per chunk (128 B/row)
#define NUM_CH (KDIM / CH_K)               // 8
#define NTILES ((MROWS / TILE_M) * (NDIM / TILE_N))   // 1024
#define NTN    (NDIM / TILE_N)             // 8
#define TBYTES (TILE_M * 128)              // 16384 per tensor
#define STAGE  (2 * TBYTES)                // A + B = 32768
#define NSTAGE 3
#define SMEM_GEMM (NSTAGE * STAGE + 16)
#define GRID_GEMM 296                      // 2 persistent CTAs per SM
#define NTHREADS 128                       // 4 warps, 2x2 grid of 64x64 tiles

// prep kernel block ranges (zero pass removed — no atomics anymore)
#define PREP_WB 4096                       // weight transpose (8E x 32n0 x 16k0)
#define PREP_AB 4096                       // input f32->fp16 cvt
#define PREP_SB 64                         // rowscale + counter
#define PREP_BLOCKS (PREP_WB + PREP_AB + PREP_SB)

__device__ __forceinline__ uint32_t smem_to_u32(const void* p) {
    uint32_t a;
    asm("{ .reg .u64 t; cvta.to.shared.u64 t, %1; cvt.u32.u64 %0, t; }"
        : "=r"(a) : "l"(p));
    return a;
}
__device__ __forceinline__ void cp_async16(uint32_t dst, const void* src) {
    asm volatile("cp.async.cg.shared.global [%0], [%1], 16;"
                 :: "r"(dst), "l"(src) : "memory");
}
__device__ __forceinline__ void cp_commit() {
    asm volatile("cp.async.commit_group;" ::: "memory");
}
template <int N>
__device__ __forceinline__ void cp_wait() {
    asm volatile("cp.async.wait_group %0;" :: "n"(N) : "memory");
}
__device__ __forceinline__ void ldm_x4(uint32_t* r, uint32_t addr) {
    asm volatile("ldmatrix.sync.aligned.m8n8.x4.shared.b16 {%0,%1,%2,%3}, [%4];"
                 : "=r"(r[0]), "=r"(r[1]), "=r"(r[2]), "=r"(r[3])
                 : "r"(addr));
}
__device__ __forceinline__ void mma_f16(float* c, const uint32_t* a,
                                        const uint32_t* b) {
    asm volatile(
        "mma.sync.aligned.m16n8k16.row.col.f32.f16.f16.f32 "
        "{%0,%1,%2,%3}, {%4,%5,%6,%7}, {%8,%9}, {%0,%1,%2,%3};"
        : "+f"(c[0]), "+f"(c[1]), "+f"(c[2]), "+f"(c[3])
        : "r"(a[0]), "r"(a[1]), "r"(a[2]), "r"(a[3]), "r"(b[0]), "r"(b[1]));
}

// Scratch (static __device__ — no allocation allowed)
__device__ uint4  d_a_h4[MROWS * KDIM / 8];           // fp16 [M,K]   (16 MB)
__device__ uint4  d_w_h4[NEXP * NDIM * KDIM / 8];     // fp16 [E,N,K] (16 MB)
__device__ __half d_g_h[MROWS * NDIM];                // fp16 [M,N]   (32 MB)
__device__ float  d_rowscale[MROWS];
__device__ int    d_tilectr;

// ---------------------------------------------------------------------------
// Kernel 1 (fused prep): weight transpose+cvt, input cvt, rowscale + counter
// ---------------------------------------------------------------------------
__global__ void k_prep(const float* __restrict__ w,
                       const float4* __restrict__ in4,
                       const int* __restrict__ splits,
                       const float* __restrict__ is,
                       const float* __restrict__ ws,
                       const float* __restrict__ ovs) {
    __shared__ float tile[32][33];
    int b = blockIdx.x;
    int tid = threadIdx.x;

    if (b < PREP_WB) {
        // weight [E,K,N] f32 -> [E,N,K] fp16 (32x32 tile via SMEM)
        int e  = b >> 9;
        int n0 = ((b >> 4) & 31) * 32;
        int k0 = (b & 15) * 32;
        int tx = tid & 31, ty = tid >> 5;   // (32, 8)
        #pragma unroll
        for (int i = 0; i < 4; i++) {
            int k = k0 + ty + 8 * i;
            tile[ty + 8 * i][tx] = w[((size_t)e * KDIM + k) * NDIM + n0 + tx];
        }
        __syncthreads();
        __half* wh = (__half*)d_w_h4;
        #pragma unroll
        for (int i = 0; i < 4; i++) {
            int n = n0 + ty + 8 * i;
            float v = tile[tx][ty + 8 * i];   // = w[e][k0+tx][n]
            size_t o = ((size_t)e * NDIM + n) * KDIM + k0 + tx;
            wh[o] = __float2half_rn(v);
        }
    } else if (b < PREP_WB + PREP_AB) {
        // input f32 -> fp16 (8 elems/thread)
        int i = (b - PREP_WB) * 256 + tid;    // uint4 (8 fp16) index
        float4 v0 = in4[2 * i], v1 = in4[2 * i + 1];
        __half2 h0 = __float22half2_rn(make_float2(v0.x, v0.y));
        __half2 h1 = __float22half2_rn(make_float2(v0.z, v0.w));
        __half2 h2 = __float22half2_rn(make_float2(v1.x, v1.y));
        __half2 h3 = __float22half2_rn(make_float2(v1.z, v1.w));
        uint4 u;
        u.x = *(uint32_t*)&h0; u.y = *(uint32_t*)&h1;
        u.z = *(uint32_t*)&h2; u.w = *(uint32_t*)&h3;
        d_a_h4[i] = u;
    } else {
        // rowscale + tile counter reset
        int m = (b - PREP_WB - PREP_AB) * 256 + tid;
        if (m == 0) d_tilectr = 0;
        if (m < MROWS) {
            int e = 0, cum = splits[0];
            while (m >= cum && e < NEXP - 1) { e++; cum += splits[e]; }
            d_rowscale[m] = is[0] * ws[e] * ovs[m];
        }
    }
}

__device__ __forceinline__ int expert_of(const int* splits, int m0) {
    int e = 0, cum = splits[0];
    while (m0 >= cum && e < NEXP - 1) { e++; cum += splits[e]; }
    return e;
}

__device__ __forceinline__ void load_chunk(uint32_t stagebase, int ch,
                                           int tid, int m0, int n0, int e) {
    const char* aT = (const char*)d_a_h4;
    const char* bT = (const char*)d_w_h4;
    // 1024 16B-chunks per tensor: row = i>>3 (128 rows), c = i&7 (8 x 16B)
    #pragma unroll
    for (int rep = 0; rep < 8; rep++) {
        int i = tid + rep * NTHREADS;
        int row = i >> 3, c = i & 7;
        uint32_t soff = row * 128 + ((c ^ (row & 7)) << 4);
        size_t ga = ((size_t)(m0 + row) * KDIM + ch * CH_K) * 2 + c * 16;
        size_t gb = (((size_t)e * NDIM + n0 + row) * KDIM + ch * CH_K) * 2 + c * 16;
        cp_async16(stagebase + soff, aT + ga);
        cp_async16(stagebase + TBYTES + soff, bT + gb);
    }
}

// ---------------------------------------------------------------------------
// Kernel 2: persistent grouped GEMM (single-pass fp16 mma m16n8k16, 64x64
// warp tiles, 3-stage cp.async ring rolling across tile boundaries, dynamic
// tile stealing; epilogue = scale + fp16 STG to dense scratch — NO atomics)
// ---------------------------------------------------------------------------
__global__ void __launch_bounds__(NTHREADS, 2)
k_moe_gemm(const int* __restrict__ splits) {
    extern __shared__ char smem[];
    uint32_t sbase = smem_to_u32(smem);
    volatile int* s_next = (volatile int*)(smem + NSTAGE * STAGE);
    int tid = threadIdx.x;
    int wid = tid >> 5;
    int lid = tid & 31;
    int wm = wid >> 1;        // 0..1  (64-row slab)
    int wn = wid & 1;         // 0..1  (64-col slab)

    // A lanes (m16n8k16): x4 tiles {r0-7,c0},{r8-15,c0},{r0-7,c1},{r8-15,c1}
    int rA = wm * 64 + (lid & 15);          // + mi*16
    int cA = lid >> 4;                      // + 2*ks
    int sA = lid & 7;                       // swizzle term (row & 7)
    // B lanes: x4 tiles {n0-7,c0},{n0-7,c1},{n8-15,c0},{n8-15,c1}
    int rB = wn * 64 + (lid & 7) + ((lid >> 4) & 1) * 8;   // + bp*16
    int cB = (lid >> 3) & 1;                // + 2*ks
    int sB = lid & 7;
    uint32_t baseA = (uint32_t)rA * 128;
    uint32_t baseB = (uint32_t)rB * 128;

    if (tid == 0) s_next[0] = atomicAdd(&d_tilectr, 1);
    __syncthreads();
    int cur = s_next[0];
    if (cur >= NTILES) return;
    int m0 = (cur / NTN) * TILE_M;
    int n0 = (cur % NTN) * TILE_N;
    int e  = expert_of(splits, m0);

    float acc[4][8][4];
    #pragma unroll
    for (int mi = 0; mi < 4; mi++)
        #pragma unroll
        for (int ni = 0; ni < 8; ni++)
            #pragma unroll
            for (int q = 0; q < 4; q++) acc[mi][ni][q] = 0.f;

    uint32_t st_c = sbase, st_n = sbase + STAGE, st_p = sbase + 2 * STAGE;
    load_chunk(st_c, 0, tid, m0, n0, e); cp_commit();
    load_chunk(st_n, 1, tid, m0, n0, e); cp_commit();

    int nxt = NTILES, nm0 = 0, nn0 = 0, ne = 0;
    while (true) {
        for (int ch = 0; ch < NUM_CH; ch++) {
            cp_wait<1>();
            __syncthreads();  // all warps done with slot st_p -> safe to refill
            if (ch == NUM_CH - 2) {          // read next tile (published ch-1)
                nxt = s_next[0];
                if (nxt < NTILES) {
                    nm0 = (nxt / NTN) * TILE_M;
                    nn0 = (nxt % NTN) * TILE_N;
                    ne  = expert_of(splits, nm0);
                }
            }
            if (ch < NUM_CH - 2) {
                load_chunk(st_p, ch + 2, tid, m0, n0, e);
            } else if (nxt < NTILES) {
                load_chunk(st_p, ch - (NUM_CH - 2), tid, nm0, nn0, ne);
            }
            cp_commit();
            if (ch == NUM_CH - 3 && tid == 0)
                s_next[0] = atomicAdd(&d_tilectr, 1);

            uint32_t A = st_c, B = st_c + TBYTES;

            #pragma unroll
            for (int ks = 0; ks < 4; ks++) {   // 4 k16-steps per 64-K chunk
                uint32_t coA = (uint32_t)(((cA + 2 * ks) ^ sA) << 4);
                uint32_t coB = (uint32_t)(((cB + 2 * ks) ^ sB) << 4);
                uint32_t a[4][4], b[4][4];
                #pragma unroll
                for (int mi = 0; mi < 4; mi++)
                    ldm_x4(a[mi], A + baseA + mi * 2048 + coA);
                #pragma unroll
                for (int bp = 0; bp < 4; bp++)
                    ldm_x4(b[bp], B + baseB + bp * 2048 + coB);
                // b[bp]: regs 0,1 = n-rows bp*16+0-7 (k0-7, k8-15);
                //        regs 2,3 = n-rows bp*16+8-15
                #pragma unroll
                for (int mi = 0; mi < 4; mi++)
                    #pragma unroll
                    for (int ni = 0; ni < 8; ni++)
                        mma_f16(acc[mi][ni], a[mi], &b[ni >> 1][(ni & 1) * 2]);
            }
            uint32_t tmp = st_c; st_c = st_n; st_n = st_p; st_p = tmp;
        }

        // epilogue: g[m][n] = fp16(acc * rowscale[m]) — dense STG, no atomics
        {
            int r0 = m0 + wm * 64 + (lid >> 2);
            int ncol0 = n0 + wn * 64 + (lid & 3) * 2;
            #pragma unroll
            for (int mi = 0; mi < 4; mi++) {
                int ma = r0 + mi * 16, mb = ma + 8;
                float sa = d_rowscale[ma], sb = d_rowscale[mb];
                #pragma unroll
                for (int ni = 0; ni < 8; ni++) {
                    int n = ncol0 + ni * 8;
                    __half2 ha = __float22half2_rn(make_float2(
                        acc[mi][ni][0] * sa, acc[mi][ni][1] * sa));
                    __half2 hb = __float22half2_rn(make_float2(
                        acc[mi][ni][2] * sb, acc[mi][ni][3] * sb));
                    *(__half2*)&d_g_h[(size_t)ma * NDIM + n] = ha;
                    *(__half2*)&d_g_h[(size_t)mb * NDIM + n] = hb;
                }
            }
        }

        if (nxt >= NTILES) break;
        cur = nxt; m0 = nm0; n0 = nn0; e = ne;
        #pragma unroll
        for (int mi = 0; mi < 4; mi++)
            #pragma unroll
            for (int ni = 0; ni < 8; ni++)
                #pragma unroll
                for (int q = 0; q < 4; q++) acc[mi][ni][q] = 0.f;
    }
    cp_wait<0>();   // drain in-flight groups before exit
}

// ---------------------------------------------------------------------------
// Kernel 3: gather  out[t] = f32(g[s0]) + f32(g[s1])   (scales pre-folded)
// ---------------------------------------------------------------------------
__global__ void k_gather(const int* __restrict__ sidx,
                         float4* __restrict__ out4) {
    int t = blockIdx.x;
    int i = threadIdx.x;                   // 256 threads, 4 cols each
    int s0 = sidx[2 * t], s1 = sidx[2 * t + 1];
    const uint2* g0 = (const uint2*)(d_g_h + (size_t)s0 * NDIM);
    const uint2* g1 = (const uint2*)(d_g_h + (size_t)s1 * NDIM);
    uint2 u0 = g0[i], u1 = g1[i];
    float2 a0 = __half22float2(*(__half2*)&u0.x);
    float2 a1 = __half22float2(*(__half2*)&u0.y);
    float2 b0 = __half22float2(*(__half2*)&u1.x);
    float2 b1 = __half22float2(*(__half2*)&u1.y);
    out4[(size_t)t * (NDIM / 4) + i] = make_float4(
        a0.x + b0.x, a0.y + b0.y, a1.x + b1.x, a1.y + b1.y);
}

extern "C" void kernel_launch(void* const* d_in, const int* in_sizes, int n_in,
                              void* d_out, int out_size) {
    const float* inp    = (const float*)d_in[0];
    const float* weight = (const float*)d_in[1];
    const int*   splits = (const int*)d_in[2];
    const int*   sidx   = (const int*)d_in[3];
    const float* iscale = (const float*)d_in[4];
    const float* wscale = (const float*)d_in[5];
    const float* ovs    = (const float*)d_in[6];
    float* out = (float*)d_out;

    cudaFuncSetAttribute(k_moe_gemm,
                         cudaFuncAttributeMaxDynamicSharedMemorySize, SMEM_GEMM);

    k_prep<<<PREP_BLOCKS, 256>>>(weight, (const float4*)inp, splits,
                                 iscale, wscale, ovs);
    k_moe_gemm<<<GRID_GEMM, NTHREADS, SMEM_GEMM>>>(splits);
    k_gather<<<NTOK, 256>>>(sidx, (float4*)out);
}

// round 16
// speedup vs baseline: 1.0509x; 1.0509x over previous
#include <cuda_runtime.h>
#include <cuda_fp16.h>
#include <cstdint>

#define NTOK 8192
#define TOPK 2
#define NEXP 8
#define KDIM 512
#define NDIM 1024
#define MROWS (NTOK * TOPK)

#define TILE_M 128
#define TILE_N 128
#define CH_K   64                          // fp16 K elems per chunk (128 B/row)
#define NUM_CH (KDIM / CH_K)               // 8
#define NTILES ((MROWS / TILE_M) * (NDIM / TILE_N))   // 1024
#define NTN    (NDIM / TILE_N)             // 8
#define TBYTES (TILE_M * 128)              // 16384 per tensor
#define STAGE  (2 * TBYTES)                // A + B = 32768
#define NSTAGE 3
#define SMEM_GEMM (NSTAGE * STAGE + 16)
#define GRID_GEMM 296                      // 2 persistent CTAs per SM
#define NTHREADS 128                       // 4 warps, 2x2 grid of 64x64 tiles

// prep kernel block ranges
#define PREP_WB 2048                       // weight transpose (8E x 32n x 8k64)
#define PREP_AB 4096                       // input f32->fp16 cvt
#define PREP_ZB 4096                       // output zero
#define PREP_SB 64                         // rowscale/inv
#define PREP_BLOCKS (PREP_WB + PREP_AB + PREP_ZB + PREP_SB)

__device__ __forceinline__ uint32_t smem_to_u32(const void* p) {
    uint32_t a;
    asm("{ .reg .u64 t; cvta.to.shared.u64 t, %1; cvt.u32.u64 %0, t; }"
        : "=r"(a) : "l"(p));
    return a;
}
__device__ __forceinline__ void cp_async16(uint32_t dst, const void* src) {
    asm volatile("cp.async.cg.shared.global [%0], [%1], 16;"
                 :: "r"(dst), "l"(src) : "memory");
}
__device__ __forceinline__ void cp_commit() {
    asm volatile("cp.async.commit_group;" ::: "memory");
}
template <int N>
__device__ __forceinline__ void cp_wait() {
    asm volatile("cp.async.wait_group %0;" :: "n"(N) : "memory");
}
__device__ __forceinline__ void ldm_x4(uint32_t* r, uint32_t addr) {
    asm volatile("ldmatrix.sync.aligned.m8n8.x4.shared.b16 {%0,%1,%2,%3}, [%4];"
                 : "=r"(r[0]), "=r"(r[1]), "=r"(r[2]), "=r"(r[3])
                 : "r"(addr));
}
__device__ __forceinline__ void mma_f16(float* c, const uint32_t* a,
                                        const uint32_t* b) {
    asm volatile(
        "mma.sync.aligned.m16n8k16.row.col.f32.f16.f16.f32 "
        "{%0,%1,%2,%3}, {%4,%5,%6,%7}, {%8,%9}, {%0,%1,%2,%3};"
        : "+f"(c[0]), "+f"(c[1]), "+f"(c[2]), "+f"(c[3])
        : "r"(a[0]), "r"(a[1]), "r"(a[2]), "r"(a[3]), "r"(b[0]), "r"(b[1]));
}
__device__ __forceinline__ void red_add_v2(float* gaddr, float x, float y) {
    asm volatile("red.global.add.v2.f32 [%0], {%1, %2};"
                 :: "l"(gaddr), "f"(x), "f"(y) : "memory");
}

// Scratch (static __device__ — no allocation allowed)
__device__ uint4  d_a_h4[MROWS * KDIM / 8];           // fp16 [M,K]   (16 MB)
__device__ uint4  d_w_h4[NEXP * NDIM * KDIM / 8];     // fp16 [E,N,K] (16 MB)
__device__ float  d_rowscale[MROWS];
__device__ int    d_inv[MROWS];
__device__ int    d_tilectr;

// ---------------------------------------------------------------------------
// Kernel 1 (fused prep): weight transpose+cvt (vectorized 16B stores),
// input cvt, zero output, rowscale + inverse scatter + counter reset.
// ---------------------------------------------------------------------------
__global__ void k_prep(const float* __restrict__ w,
                       const float4* __restrict__ in4,
                       float4* __restrict__ out4,
                       const int* __restrict__ splits,
                       const int* __restrict__ sidx,
                       const float* __restrict__ is,
                       const float* __restrict__ ws,
                       const float* __restrict__ ovs) {
    __shared__ float tile[64][33];          // [k][n], pad 33 (conflict-free cols)
    int b = blockIdx.x;
    int tid = threadIdx.x;

    if (b < PREP_WB) {
        // weight [E,K,N] f32 -> [E,N,K] fp16; block = 64 k-rows x 32 n-cols
        int e  = b >> 8;                    // 256 blocks per expert
        int n0 = ((b >> 3) & 31) * 32;      // 32 n-tiles
        int k0 = (b & 7) * 64;              // 8 k-tiles
        // load: 64 rows x 32 f32, coalesced (tx = n)
        int tx = tid & 31, ty = tid >> 5;   // (32, 8)
        #pragma unroll
        for (int i = 0; i < 8; i++) {
            int k = ty + 8 * i;             // 0..63
            tile[k][tx] = w[((size_t)e * KDIM + k0 + k) * NDIM + n0 + tx];
        }
        __syncthreads();
        // store: thread = (n, k-octet); pack 8 k-values -> one uint4 (16B)
        int n = tid >> 3, ko = (tid & 7) * 8;
        __half2 h[4];
        #pragma unroll
        for (int j = 0; j < 4; j++)
            h[j] = __float22half2_rn(make_float2(tile[ko + 2 * j][n],
                                                 tile[ko + 2 * j + 1][n]));
        uint4 u;
        u.x = *(uint32_t*)&h[0]; u.y = *(uint32_t*)&h[1];
        u.z = *(uint32_t*)&h[2]; u.w = *(uint32_t*)&h[3];
        // element offset (e*NDIM + n0+n)*KDIM + k0 + ko, in uint4 units (/8)
        d_w_h4[(((size_t)e * NDIM + n0 + n) * KDIM + k0 + ko) >> 3] = u;
    } else if (b < PREP_WB + PREP_AB) {
        // input f32 -> fp16 (8 elems/thread)
        int i = (b - PREP_WB) * 256 + tid;    // uint4 (8 fp16) index
        float4 v0 = in4[2 * i], v1 = in4[2 * i + 1];
        __half2 h0 = __float22half2_rn(make_float2(v0.x, v0.y));
        __half2 h1 = __float22half2_rn(make_float2(v0.z, v0.w));
        __half2 h2 = __float22half2_rn(make_float2(v1.x, v1.y));
        __half2 h3 = __float22half2_rn(make_float2(v1.z, v1.w));
        uint4 u;
        u.x = *(uint32_t*)&h0; u.y = *(uint32_t*)&h1;
        u.z = *(uint32_t*)&h2; u.w = *(uint32_t*)&h3;
        d_a_h4[i] = u;
    } else if (b < PREP_WB + PREP_AB + PREP_ZB) {
        // zero output: 512 float4 per block (2 per thread)
        int i = (b - PREP_WB - PREP_AB) * 512 + tid * 2;
        out4[i]     = make_float4(0.f, 0.f, 0.f, 0.f);
        out4[i + 1] = make_float4(0.f, 0.f, 0.f, 0.f);
    } else {
        // rowscale + inverse scatter index + tile counter reset
        int m = (b - PREP_WB - PREP_AB - PREP_ZB) * 256 + tid;
        if (m == 0) d_tilectr = 0;
        if (m < MROWS) {
            int e = 0, cum = splits[0];
            while (m >= cum && e < NEXP - 1) { e++; cum += splits[e]; }
            d_rowscale[m] = is[0] * ws[e] * ovs[m];
            d_inv[sidx[m]] = m / TOPK;
        }
    }
}

__device__ __forceinline__ int expert_of(const int* splits, int m0) {
    int e = 0, cum = splits[0];
    while (m0 >= cum && e < NEXP - 1) { e++; cum += splits[e]; }
    return e;
}

__device__ __forceinline__ void load_chunk(uint32_t stagebase, int ch,
                                           int tid, int m0, int n0, int e) {
    const char* aT = (const char*)d_a_h4;
    const char* bT = (const char*)d_w_h4;
    // 1024 16B-chunks per tensor: row = i>>3 (128 rows), c = i&7 (8 x 16B)
    #pragma unroll
    for (int rep = 0; rep < 8; rep++) {
        int i = tid + rep * NTHREADS;
        int row = i >> 3, c = i & 7;
        uint32_t soff = row * 128 + ((c ^ (row & 7)) << 4);
        size_t ga = ((size_t)(m0 + row) * KDIM + ch * CH_K) * 2 + c * 16;
        size_t gb = (((size_t)e * NDIM + n0 + row) * KDIM + ch * CH_K) * 2 + c * 16;
        cp_async16(stagebase + soff, aT + ga);
        cp_async16(stagebase + TBYTES + soff, bT + gb);
    }
}

// ---------------------------------------------------------------------------
// Kernel 2: persistent grouped GEMM (single-pass fp16 mma m16n8k16, 64x64
// warp tiles, 3-stage cp.async ring rolling across tile boundaries, dynamic
// tile stealing, fused scale + scatter-reduce epilogue via red.global)
// [R12 body verbatim — the 79.9us champion]
// ---------------------------------------------------------------------------
__global__ void __launch_bounds__(NTHREADS, 2)
k_moe_gemm(const int* __restrict__ splits, float* __restrict__ out) {
    extern __shared__ char smem[];
    uint32_t sbase = smem_to_u32(smem);
    volatile int* s_next = (volatile int*)(smem + NSTAGE * STAGE);
    int tid = threadIdx.x;
    int wid = tid >> 5;
    int lid = tid & 31;
    int wm = wid >> 1;        // 0..1  (64-row slab)
    int wn = wid & 1;         // 0..1  (64-col slab)

    // A lanes (m16n8k16): x4 tiles {r0-7,c0},{r8-15,c0},{r0-7,c1},{r8-15,c1}
    int rA = wm * 64 + (lid & 15);          // + mi*16
    int cA = lid >> 4;                      // + 2*ks
    int sA = lid & 7;                       // swizzle term (row & 7)
    // B lanes: x4 tiles {n0-7,c0},{n0-7,c1},{n8-15,c0},{n8-15,c1}
    int rB = wn * 64 + (lid & 7) + ((lid >> 4) & 1) * 8;   // + bp*16
    int cB = (lid >> 3) & 1;                // + 2*ks
    int sB = lid & 7;
    uint32_t baseA = (uint32_t)rA * 128;
    uint32_t baseB = (uint32_t)rB * 128;

    if (tid == 0) s_next[0] = atomicAdd(&d_tilectr, 1);
    __syncthreads();
    int cur = s_next[0];
    if (cur >= NTILES) return;
    int m0 = (cur / NTN) * TILE_M;
    int n0 = (cur % NTN) * TILE_N;
    int e  = expert_of(splits, m0);

    float acc[4][8][4];
    #pragma unroll
    for (int mi = 0; mi < 4; mi++)
        #pragma unroll
        for (int ni = 0; ni < 8; ni++)
            #pragma unroll
            for (int q = 0; q < 4; q++) acc[mi][ni][q] = 0.f;

    uint32_t st_c = sbase, st_n = sbase + STAGE, st_p = sbase + 2 * STAGE;
    load_chunk(st_c, 0, tid, m0, n0, e); cp_commit();
    load_chunk(st_n, 1, tid, m0, n0, e); cp_commit();

    int nxt = NTILES, nm0 = 0, nn0 = 0, ne = 0;
    while (true) {
        for (int ch = 0; ch < NUM_CH; ch++) {
            cp_wait<1>();
            __syncthreads();  // all warps done with slot st_p -> safe to refill
            if (ch == NUM_CH - 2) {          // read next tile (published ch-1)
                nxt = s_next[0];
                if (nxt < NTILES) {
                    nm0 = (nxt / NTN) * TILE_M;
                    nn0 = (nxt % NTN) * TILE_N;
                    ne  = expert_of(splits, nm0);
                }
            }
            if (ch < NUM_CH - 2) {
                load_chunk(st_p, ch + 2, tid, m0, n0, e);
            } else if (nxt < NTILES) {
                load_chunk(st_p, ch - (NUM_CH - 2), tid, nm0, nn0, ne);
            }
            cp_commit();
            if (ch == NUM_CH - 3 && tid == 0)
                s_next[0] = atomicAdd(&d_tilectr, 1);

            uint32_t A = st_c, B = st_c + TBYTES;

            #pragma unroll
            for (int ks = 0; ks < 4; ks++) {   // 4 k16-steps per 64-K chunk
                uint32_t coA = (uint32_t)(((cA + 2 * ks) ^ sA) << 4);
                uint32_t coB = (uint32_t)(((cB + 2 * ks) ^ sB) << 4);
                uint32_t a[4][4], b[4][4];
                #pragma unroll
                for (int mi = 0; mi < 4; mi++)
                    ldm_x4(a[mi], A + baseA + mi * 2048 + coA);
                #pragma unroll
                for (int bp = 0; bp < 4; bp++)
                    ldm_x4(b[bp], B + baseB + bp * 2048 + coB);
                // b[bp]: regs 0,1 = n-rows bp*16+0-7 (k0-7, k8-15);
                //        regs 2,3 = n-rows bp*16+8-15
                #pragma unroll
                for (int mi = 0; mi < 4; mi++)
                    #pragma unroll
                    for (int ni = 0; ni < 8; ni++)
                        mma_f16(acc[mi][ni], a[mi], &b[ni >> 1][(ni & 1) * 2]);
            }
            uint32_t tmp = st_c; st_c = st_n; st_n = st_p; st_p = tmp;
        }

        // fused epilogue: out[inv[m]] += acc * rowscale[m]  (scatter-reduce)
        {
            int r0 = m0 + wm * 64 + (lid >> 2);
            int ncol0 = n0 + wn * 64 + (lid & 3) * 2;
            #pragma unroll
            for (int mi = 0; mi < 4; mi++) {
                int ma = r0 + mi * 16, mb = ma + 8;
                int   ta = d_inv[ma],      tb = d_inv[mb];
                float sa = d_rowscale[ma], sb = d_rowscale[mb];
                #pragma unroll
                for (int ni = 0; ni < 8; ni++) {
                    int n = ncol0 + ni * 8;
                    red_add_v2(&out[(size_t)ta * NDIM + n],
                               acc[mi][ni][0] * sa, acc[mi][ni][1] * sa);
                    red_add_v2(&out[(size_t)tb * NDIM + n],
                               acc[mi][ni][2] * sb, acc[mi][ni][3] * sb);
                }
            }
        }

        if (nxt >= NTILES) break;
        cur = nxt; m0 = nm0; n0 = nn0; e = ne;
        #pragma unroll
        for (int mi = 0; mi < 4; mi++)
            #pragma unroll
            for (int ni = 0; ni < 8; ni++)
                #pragma unroll
                for (int q = 0; q < 4; q++) acc[mi][ni][q] = 0.f;
    }
    cp_wait<0>();   // drain in-flight groups before exit
}

extern "C" void kernel_launch(void* const* d_in, const int* in_sizes, int n_in,
                              void* d_out, int out_size) {
    const float* inp    = (const float*)d_in[0];
    const float* weight = (const float*)d_in[1];
    const int*   splits = (const int*)d_in[2];
    const int*   sidx   = (const int*)d_in[3];
    const float* iscale = (const float*)d_in[4];
    const float* wscale = (const float*)d_in[5];
    const float* ovs    = (const float*)d_in[6];
    float* out = (float*)d_out;

    cudaFuncSetAttribute(k_moe_gemm,
                         cudaFuncAttributeMaxDynamicSharedMemorySize, SMEM_GEMM);

    k_prep<<<PREP_BLOCKS, 256>>>(weight, (const float4*)inp, (float4*)out,
                                 splits, sidx, iscale, wscale, ovs);
    k_moe_gemm<<<GRID_GEMM, NTHREADS, SMEM_GEMM>>>(splits, out);
}